// round 7
// baseline (speedup 1.0000x reference)
#include <cuda_runtime.h>
#include <cuda_bf16.h>

#define N_RES 1024
#define C_M   256
#define C_Z   128
#define NUM_BINS 15
#define LN_EPS 1e-5f
#define ROWS_PER_WARP 4

// Fused distogram+bias table: g_dtab[k][c] = ln_z_b[c] + lin_b[c] + (k<15 ? lin_w[c,k] : 0)
__device__ float g_dtab[16 * C_Z];

// ---------------------------------------------------------------------------
// Kernel 1: m LayerNorm (blocks 0..127, one warp per row) + dtab build
// (blocks 128..135, one element per thread). Single launch replaces two.
// ---------------------------------------------------------------------------
__global__ void __launch_bounds__(256) m_ln_dtab_kernel(
    const float* __restrict__ m,
    const float* __restrict__ w,
    const float* __restrict__ b,
    const float* __restrict__ ln_z_b,
    const float* __restrict__ lin_w,
    const float* __restrict__ lin_b,
    float* __restrict__ out)
{
    if (blockIdx.x >= 128) {
        // dtab build: 8 blocks * 256 threads = 2048 entries
        int idx = (blockIdx.x - 128) * 256 + threadIdx.x;   // 0..2047
        int k = idx >> 7;
        int c = idx & (C_Z - 1);
        float v = ln_z_b[c] + lin_b[c];
        if (k < NUM_BINS) v += lin_w[c * NUM_BINS + k];
        g_dtab[idx] = v;
        return;
    }

    int warp = (blockIdx.x * 256 + threadIdx.x) >> 5;   // 0..1023
    int lane = threadIdx.x & 31;

    const float4* row = reinterpret_cast<const float4*>(m + (size_t)warp * C_M);
    float4 v0 = row[lane];
    float4 v1 = row[lane + 32];

    float s  = v0.x + v0.y + v0.z + v0.w + v1.x + v1.y + v1.z + v1.w;
    float s2 = v0.x*v0.x + v0.y*v0.y + v0.z*v0.z + v0.w*v0.w
             + v1.x*v1.x + v1.y*v1.y + v1.z*v1.z + v1.w*v1.w;
#pragma unroll
    for (int o = 16; o; o >>= 1) {
        s  += __shfl_xor_sync(0xffffffffu, s,  o);
        s2 += __shfl_xor_sync(0xffffffffu, s2, o);
    }
    float mu  = s * (1.0f / C_M);
    float var = s2 * (1.0f / C_M) - mu * mu;
    float inv = rsqrtf(var + LN_EPS);

    float4* orow = reinterpret_cast<float4*>(out + (size_t)warp * C_M);
    int c0 = lane * 4;
    float4 r0, r1;
    r0.x = (v0.x - mu) * inv * w[c0 + 0]   + b[c0 + 0];
    r0.y = (v0.y - mu) * inv * w[c0 + 1]   + b[c0 + 1];
    r0.z = (v0.z - mu) * inv * w[c0 + 2]   + b[c0 + 2];
    r0.w = (v0.w - mu) * inv * w[c0 + 3]   + b[c0 + 3];
    r1.x = (v1.x - mu) * inv * w[c0 + 128] + b[c0 + 128];
    r1.y = (v1.y - mu) * inv * w[c0 + 129] + b[c0 + 129];
    r1.z = (v1.z - mu) * inv * w[c0 + 130] + b[c0 + 130];
    r1.w = (v1.w - mu) * inv * w[c0 + 131] + b[c0 + 131];
    orow[lane]      = r0;
    orow[lane + 32] = r1;
}

// ---------------------------------------------------------------------------
// Kernel 2: z LayerNorm + distogram add. One warp per 4 consecutive (i,j)
// rows. All per-channel constants folded into g_dtab; ln weight in registers.
// Reductions for all 4 rows interleaved -> 8 independent SHFL chains (ILP).
// ---------------------------------------------------------------------------
__global__ void __launch_bounds__(512) z_fused_kernel(
    const float* __restrict__ z,
    const float* __restrict__ x,
    const float* __restrict__ lnw,
    float* __restrict__ out)
{
    int lane = threadIdx.x & 31;
    long long row0 = (long long)((blockIdx.x * 512 + threadIdx.x) >> 5)
                   * ROWS_PER_WARP;
    int i  = (int)(row0 >> 10);
    int j0 = (int)(row0 & (N_RES - 1));   // row0 % 4 == 0 -> same i for all 4 rows

    // Front-batched streaming loads (MLP=4)
    const float4* zr = reinterpret_cast<const float4*>(z + row0 * C_Z) + lane;
    float4 v[ROWS_PER_WARP];
#pragma unroll
    for (int r = 0; r < ROWS_PER_WARP; ++r)
        v[r] = __ldcs(zr + r * 32);

    // Bin index per row (warp-uniform, arithmetic instead of 15-way loop)
    float xi0 = x[3 * i + 0], xi1 = x[3 * i + 1], xi2 = x[3 * i + 2];
    int kb[ROWS_PER_WARP];
#pragma unroll
    for (int r = 0; r < ROWS_PER_WARP; ++r) {
        int j = j0 + r;
        float dx = xi0 - x[3 * j + 0];
        float dy = xi1 - x[3 * j + 1];
        float dz = xi2 - x[3 * j + 2];
        float d2 = dx * dx + dy * dy + dz * dz;
        int kk = __float2int_rd((__fsqrt_rn(d2) - 3.25f) * 0.8f);
        kk = min(max(kk, 0), NUM_BINS - 1);
        kb[r] = (d2 <= 10.5625f) ? NUM_BINS : kk;   // 10.5625 = 3.25^2
    }

    // Interleaved reductions: 8 independent shuffle chains
    float s[ROWS_PER_WARP], s2[ROWS_PER_WARP];
#pragma unroll
    for (int r = 0; r < ROWS_PER_WARP; ++r) {
        float4 vv = v[r];
        s[r]  = vv.x + vv.y + vv.z + vv.w;
        s2[r] = vv.x*vv.x + vv.y*vv.y + vv.z*vv.z + vv.w*vv.w;
    }
#pragma unroll
    for (int o = 16; o; o >>= 1) {
#pragma unroll
        for (int r = 0; r < ROWS_PER_WARP; ++r) {
            s[r]  += __shfl_xor_sync(0xffffffffu, s[r],  o);
            s2[r] += __shfl_xor_sync(0xffffffffu, s2[r], o);
        }
    }

    int c0 = lane * 4;
    float4 sw4 = *reinterpret_cast<const float4*>(lnw + c0);
    float4* orow = reinterpret_cast<float4*>(out + row0 * C_Z) + lane;

#pragma unroll
    for (int r = 0; r < ROWS_PER_WARP; ++r) {
        float mu  = s[r] * (1.0f / C_Z);
        float var = s2[r] * (1.0f / C_Z) - mu * mu;
        float inv = rsqrtf(var + LN_EPS);

        float4 d4 = *reinterpret_cast<const float4*>(g_dtab + kb[r] * C_Z + c0);
        float4 vv = v[r];
        float4 o;
        o.x = (vv.x - mu) * (inv * sw4.x) + d4.x;
        o.y = (vv.y - mu) * (inv * sw4.y) + d4.y;
        o.z = (vv.z - mu) * (inv * sw4.z) + d4.z;
        o.w = (vv.w - mu) * (inv * sw4.w) + d4.w;
        __stcs(orow + r * 32, o);
    }
}

extern "C" void kernel_launch(void* const* d_in, const int* in_sizes, int n_in,
                              void* d_out, int out_size)
{
    const float* m      = (const float*)d_in[0];
    const float* z      = (const float*)d_in[1];
    const float* x      = (const float*)d_in[2];
    const float* ln_m_w = (const float*)d_in[3];
    const float* ln_m_b = (const float*)d_in[4];
    const float* ln_z_w = (const float*)d_in[5];
    const float* ln_z_b = (const float*)d_in[6];
    const float* lin_w  = (const float*)d_in[7];
    const float* lin_b  = (const float*)d_in[8];

    float* out_m = (float*)d_out;                   // [N_RES, C_M]
    float* out_z = out_m + (size_t)N_RES * C_M;     // [N_RES, N_RES, C_Z]

    // 128 m-blocks + 8 dtab-blocks in one launch
    m_ln_dtab_kernel<<<136, 256>>>(m, ln_m_w, ln_m_b, ln_z_b, lin_w, lin_b, out_m);

    // 1M rows / (16 warps * 4 rows) = 16384 blocks
    z_fused_kernel<<<(N_RES * N_RES) / (16 * ROWS_PER_WARP), 512>>>(
        z, x, ln_z_w, out_z);
}

// round 8
// speedup vs baseline: 1.2425x; 1.2425x over previous
#include <cuda_runtime.h>
#include <cuda_bf16.h>

#define N_RES 1024
#define C_M   256
#define C_Z   128
#define NUM_BINS 15
#define LN_EPS 1e-5f
#define ROWS_PER_WARP 4

// Fused distogram+bias table: g_dtab[k][c] = ln_z_b[c] + lin_b[c] + (k<15 ? lin_w[c,k] : 0)
__device__ float g_dtab[16 * C_Z];

// ---------------------------------------------------------------------------
// Kernel 1: m LayerNorm (blocks 0..127, one warp per row) + dtab build
// (blocks 128..135, one element per thread). Single launch replaces two.
// ---------------------------------------------------------------------------
__global__ void __launch_bounds__(256) m_ln_dtab_kernel(
    const float* __restrict__ m,
    const float* __restrict__ w,
    const float* __restrict__ b,
    const float* __restrict__ ln_z_b,
    const float* __restrict__ lin_w,
    const float* __restrict__ lin_b,
    float* __restrict__ out)
{
    if (blockIdx.x >= 128) {
        // dtab build: 8 blocks * 256 threads = 2048 entries
        int idx = (blockIdx.x - 128) * 256 + threadIdx.x;   // 0..2047
        int k = idx >> 7;
        int c = idx & (C_Z - 1);
        float v = ln_z_b[c] + lin_b[c];
        if (k < NUM_BINS) v += lin_w[c * NUM_BINS + k];
        g_dtab[idx] = v;
        return;
    }

    int warp = (blockIdx.x * 256 + threadIdx.x) >> 5;   // 0..1023
    int lane = threadIdx.x & 31;

    const float4* row = reinterpret_cast<const float4*>(m + (size_t)warp * C_M);
    float4 v0 = row[lane];
    float4 v1 = row[lane + 32];

    float s  = v0.x + v0.y + v0.z + v0.w + v1.x + v1.y + v1.z + v1.w;
    float s2 = v0.x*v0.x + v0.y*v0.y + v0.z*v0.z + v0.w*v0.w
             + v1.x*v1.x + v1.y*v1.y + v1.z*v1.z + v1.w*v1.w;
#pragma unroll
    for (int o = 16; o; o >>= 1) {
        s  += __shfl_xor_sync(0xffffffffu, s,  o);
        s2 += __shfl_xor_sync(0xffffffffu, s2, o);
    }
    float mu  = s * (1.0f / C_M);
    float var = s2 * (1.0f / C_M) - mu * mu;
    float inv = rsqrtf(var + LN_EPS);

    float4* orow = reinterpret_cast<float4*>(out + (size_t)warp * C_M);
    int c0 = lane * 4;
    float4 r0, r1;
    r0.x = (v0.x - mu) * inv * w[c0 + 0]   + b[c0 + 0];
    r0.y = (v0.y - mu) * inv * w[c0 + 1]   + b[c0 + 1];
    r0.z = (v0.z - mu) * inv * w[c0 + 2]   + b[c0 + 2];
    r0.w = (v0.w - mu) * inv * w[c0 + 3]   + b[c0 + 3];
    r1.x = (v1.x - mu) * inv * w[c0 + 128] + b[c0 + 128];
    r1.y = (v1.y - mu) * inv * w[c0 + 129] + b[c0 + 129];
    r1.z = (v1.z - mu) * inv * w[c0 + 130] + b[c0 + 130];
    r1.w = (v1.w - mu) * inv * w[c0 + 131] + b[c0 + 131];
    orow[lane]      = r0;
    orow[lane + 32] = r1;
}

// ---------------------------------------------------------------------------
// Kernel 2: z LayerNorm + distogram add. One warp per 4 consecutive (i,j)
// rows, 8 warps / 256-thread block (R3 config: occ ~92%, DRAM ~80%).
// All per-channel constants folded into g_dtab; ln weight in registers.
// Reductions for all 4 rows interleaved -> 8 independent SHFL chains (ILP).
// ---------------------------------------------------------------------------
__global__ void __launch_bounds__(256) z_fused_kernel(
    const float* __restrict__ z,
    const float* __restrict__ x,
    const float* __restrict__ lnw,
    float* __restrict__ out)
{
    int lane = threadIdx.x & 31;
    long long row0 = (long long)((blockIdx.x * 256 + threadIdx.x) >> 5)
                   * ROWS_PER_WARP;
    int i  = (int)(row0 >> 10);
    int j0 = (int)(row0 & (N_RES - 1));   // row0 % 4 == 0 -> same i for all 4 rows

    // Front-batched streaming loads (MLP=4)
    const float4* zr = reinterpret_cast<const float4*>(z + row0 * C_Z) + lane;
    float4 v[ROWS_PER_WARP];
#pragma unroll
    for (int r = 0; r < ROWS_PER_WARP; ++r)
        v[r] = __ldcs(zr + r * 32);

    // Bin index per row (warp-uniform, arithmetic instead of 15-way loop)
    float xi0 = x[3 * i + 0], xi1 = x[3 * i + 1], xi2 = x[3 * i + 2];
    int kb[ROWS_PER_WARP];
#pragma unroll
    for (int r = 0; r < ROWS_PER_WARP; ++r) {
        int j = j0 + r;
        float dx = xi0 - x[3 * j + 0];
        float dy = xi1 - x[3 * j + 1];
        float dz = xi2 - x[3 * j + 2];
        float d2 = dx * dx + dy * dy + dz * dz;
        int kk = __float2int_rd((__fsqrt_rn(d2) - 3.25f) * 0.8f);
        kk = min(max(kk, 0), NUM_BINS - 1);
        kb[r] = (d2 <= 10.5625f) ? NUM_BINS : kk;   // 10.5625 = 3.25^2
    }

    // Interleaved reductions: 8 independent shuffle chains
    float s[ROWS_PER_WARP], s2[ROWS_PER_WARP];
#pragma unroll
    for (int r = 0; r < ROWS_PER_WARP; ++r) {
        float4 vv = v[r];
        s[r]  = vv.x + vv.y + vv.z + vv.w;
        s2[r] = vv.x*vv.x + vv.y*vv.y + vv.z*vv.z + vv.w*vv.w;
    }
#pragma unroll
    for (int o = 16; o; o >>= 1) {
#pragma unroll
        for (int r = 0; r < ROWS_PER_WARP; ++r) {
            s[r]  += __shfl_xor_sync(0xffffffffu, s[r],  o);
            s2[r] += __shfl_xor_sync(0xffffffffu, s2[r], o);
        }
    }

    int c0 = lane * 4;
    float4 sw4 = *reinterpret_cast<const float4*>(lnw + c0);
    float4* orow = reinterpret_cast<float4*>(out + row0 * C_Z) + lane;

#pragma unroll
    for (int r = 0; r < ROWS_PER_WARP; ++r) {
        float mu  = s[r] * (1.0f / C_Z);
        float var = s2[r] * (1.0f / C_Z) - mu * mu;
        float inv = rsqrtf(var + LN_EPS);

        float4 d4 = *reinterpret_cast<const float4*>(g_dtab + kb[r] * C_Z + c0);
        float4 vv = v[r];
        float4 o;
        o.x = (vv.x - mu) * (inv * sw4.x) + d4.x;
        o.y = (vv.y - mu) * (inv * sw4.y) + d4.y;
        o.z = (vv.z - mu) * (inv * sw4.z) + d4.z;
        o.w = (vv.w - mu) * (inv * sw4.w) + d4.w;
        __stcs(orow + r * 32, o);
    }
}

extern "C" void kernel_launch(void* const* d_in, const int* in_sizes, int n_in,
                              void* d_out, int out_size)
{
    const float* m      = (const float*)d_in[0];
    const float* z      = (const float*)d_in[1];
    const float* x      = (const float*)d_in[2];
    const float* ln_m_w = (const float*)d_in[3];
    const float* ln_m_b = (const float*)d_in[4];
    const float* ln_z_w = (const float*)d_in[5];
    const float* ln_z_b = (const float*)d_in[6];
    const float* lin_w  = (const float*)d_in[7];
    const float* lin_b  = (const float*)d_in[8];

    float* out_m = (float*)d_out;                   // [N_RES, C_M]
    float* out_z = out_m + (size_t)N_RES * C_M;     // [N_RES, N_RES, C_Z]

    // 128 m-blocks + 8 dtab-blocks in one launch
    m_ln_dtab_kernel<<<136, 256>>>(m, ln_m_w, ln_m_b, ln_z_b, lin_w, lin_b, out_m);

    // 1M rows / (8 warps * 4 rows) = 32768 blocks
    z_fused_kernel<<<(N_RES * N_RES) / (8 * ROWS_PER_WARP), 256>>>(
        z, x, ln_z_w, out_z);
}

// round 11
// speedup vs baseline: 1.2531x; 1.0085x over previous
#include <cuda_runtime.h>
#include <cuda_bf16.h>

#define N_RES 1024
#define C_M   256
#define C_Z   128
#define NUM_BINS 15
#define LN_EPS 1e-5f
#define ROWS_PER_WARP 4
#define M_BLOCKS 128

// ---------------------------------------------------------------------------
// Single fused kernel.
//   blocks [0, 128)        : m LayerNorm, one warp per row (8 rows/block)
//   blocks [128, 128+32768): z LayerNorm + distogram add, 8 warps x 4 rows.
// z-blocks build the fused distogram table (ln_z_b + lin_b + lin_w[:,k])
// in shared memory -> no cross-kernel dependency, one launch total.
// ---------------------------------------------------------------------------
__global__ void __launch_bounds__(256) fused_kernel(
    const float* __restrict__ m,
    const float* __restrict__ ln_m_w,
    const float* __restrict__ ln_m_b,
    const float* __restrict__ z,
    const float* __restrict__ x,
    const float* __restrict__ ln_z_w,
    const float* __restrict__ ln_z_b,
    const float* __restrict__ lin_w,
    const float* __restrict__ lin_b,
    float* __restrict__ out_m,
    float* __restrict__ out_z)
{
    int tid  = threadIdx.x;
    int lane = tid & 31;

    if (blockIdx.x < M_BLOCKS) {
        // ---------------- m LayerNorm ----------------
        int row = blockIdx.x * 8 + (tid >> 5);   // 0..1023
        const float4* rp = reinterpret_cast<const float4*>(m + (size_t)row * C_M);
        float4 v0 = rp[lane];
        float4 v1 = rp[lane + 32];

        float s  = v0.x + v0.y + v0.z + v0.w + v1.x + v1.y + v1.z + v1.w;
        float s2 = v0.x*v0.x + v0.y*v0.y + v0.z*v0.z + v0.w*v0.w
                 + v1.x*v1.x + v1.y*v1.y + v1.z*v1.z + v1.w*v1.w;
#pragma unroll
        for (int o = 16; o; o >>= 1) {
            s  += __shfl_xor_sync(0xffffffffu, s,  o);
            s2 += __shfl_xor_sync(0xffffffffu, s2, o);
        }
        float mu  = s * (1.0f / C_M);
        float var = s2 * (1.0f / C_M) - mu * mu;
        float inv = rsqrtf(var + LN_EPS);

        float4* orow = reinterpret_cast<float4*>(out_m + (size_t)row * C_M);
        int c0 = lane * 4;
        float4 r0, r1;
        r0.x = (v0.x - mu) * inv * ln_m_w[c0 + 0]   + ln_m_b[c0 + 0];
        r0.y = (v0.y - mu) * inv * ln_m_w[c0 + 1]   + ln_m_b[c0 + 1];
        r0.z = (v0.z - mu) * inv * ln_m_w[c0 + 2]   + ln_m_b[c0 + 2];
        r0.w = (v0.w - mu) * inv * ln_m_w[c0 + 3]   + ln_m_b[c0 + 3];
        r1.x = (v1.x - mu) * inv * ln_m_w[c0 + 128] + ln_m_b[c0 + 128];
        r1.y = (v1.y - mu) * inv * ln_m_w[c0 + 129] + ln_m_b[c0 + 129];
        r1.z = (v1.z - mu) * inv * ln_m_w[c0 + 130] + ln_m_b[c0 + 130];
        r1.w = (v1.w - mu) * inv * ln_m_w[c0 + 131] + ln_m_b[c0 + 131];
        orow[lane]      = r0;
        orow[lane + 32] = r1;
        return;
    }

    // ---------------- z LayerNorm + distogram ----------------
    __shared__ float sdtab[16 * C_Z];

    // Build fused table: sdtab[k*128+c] = ln_z_b[c] + lin_b[c] + (k<15 ? lin_w[c,k] : 0)
    {
        int c = tid & (C_Z - 1);
        float base = ln_z_b[c] + lin_b[c];
#pragma unroll
        for (int i = 0; i < 8; ++i) {
            int idx = tid + i * 256;
            int k = idx >> 7;
            float v = base;
            if (k < NUM_BINS) v += lin_w[c * NUM_BINS + k];
            sdtab[idx] = v;
        }
    }
    __syncthreads();

    long long row0 = (long long)(((blockIdx.x - M_BLOCKS) * 256 + tid) >> 5)
                   * ROWS_PER_WARP;
    int i  = (int)(row0 >> 10);
    int j0 = (int)(row0 & (N_RES - 1));   // row0 % 4 == 0 -> same i for all 4 rows

    // Front-batched streaming loads (MLP=4)
    const float4* zr = reinterpret_cast<const float4*>(z + row0 * C_Z) + lane;
    float4 v[ROWS_PER_WARP];
#pragma unroll
    for (int r = 0; r < ROWS_PER_WARP; ++r)
        v[r] = __ldcs(zr + r * 32);

    // Bin index per row (warp-uniform, arithmetic)
    float xi0 = x[3 * i + 0], xi1 = x[3 * i + 1], xi2 = x[3 * i + 2];
    int kb[ROWS_PER_WARP];
#pragma unroll
    for (int r = 0; r < ROWS_PER_WARP; ++r) {
        int j = j0 + r;
        float dx = xi0 - x[3 * j + 0];
        float dy = xi1 - x[3 * j + 1];
        float dz = xi2 - x[3 * j + 2];
        float d2 = dx * dx + dy * dy + dz * dz;
        int kk = __float2int_rd((__fsqrt_rn(d2) - 3.25f) * 0.8f);
        kk = min(max(kk, 0), NUM_BINS - 1);
        kb[r] = (d2 <= 10.5625f) ? NUM_BINS : kk;   // 10.5625 = 3.25^2
    }

    // Interleaved reductions: 8 independent shuffle chains
    float s[ROWS_PER_WARP], s2[ROWS_PER_WARP];
#pragma unroll
    for (int r = 0; r < ROWS_PER_WARP; ++r) {
        float4 vv = v[r];
        s[r]  = vv.x + vv.y + vv.z + vv.w;
        s2[r] = vv.x*vv.x + vv.y*vv.y + vv.z*vv.z + vv.w*vv.w;
    }
#pragma unroll
    for (int o = 16; o; o >>= 1) {
#pragma unroll
        for (int r = 0; r < ROWS_PER_WARP; ++r) {
            s[r]  += __shfl_xor_sync(0xffffffffu, s[r],  o);
            s2[r] += __shfl_xor_sync(0xffffffffu, s2[r], o);
        }
    }

    int c0 = lane * 4;
    float4 sw4 = *reinterpret_cast<const float4*>(ln_z_w + c0);
    float4* orow = reinterpret_cast<float4*>(out_z + row0 * C_Z) + lane;

#pragma unroll
    for (int r = 0; r < ROWS_PER_WARP; ++r) {
        float mu  = s[r] * (1.0f / C_Z);
        float var = s2[r] * (1.0f / C_Z) - mu * mu;
        float inv = rsqrtf(var + LN_EPS);

        float4 d4 = *reinterpret_cast<const float4*>(sdtab + kb[r] * C_Z + c0);
        float4 vv = v[r];
        float4 o;
        o.x = (vv.x - mu) * (inv * sw4.x) + d4.x;
        o.y = (vv.y - mu) * (inv * sw4.y) + d4.y;
        o.z = (vv.z - mu) * (inv * sw4.z) + d4.z;
        o.w = (vv.w - mu) * (inv * sw4.w) + d4.w;
        __stcs(orow + r * 32, o);
    }
}

extern "C" void kernel_launch(void* const* d_in, const int* in_sizes, int n_in,
                              void* d_out, int out_size)
{
    const float* m      = (const float*)d_in[0];
    const float* z      = (const float*)d_in[1];
    const float* x      = (const float*)d_in[2];
    const float* ln_m_w = (const float*)d_in[3];
    const float* ln_m_b = (const float*)d_in[4];
    const float* ln_z_w = (const float*)d_in[5];
    const float* ln_z_b = (const float*)d_in[6];
    const float* lin_w  = (const float*)d_in[7];
    const float* lin_b  = (const float*)d_in[8];

    float* out_m = (float*)d_out;                   // [N_RES, C_M]
    float* out_z = out_m + (size_t)N_RES * C_M;     // [N_RES, N_RES, C_Z]

    int z_blocks = (N_RES * N_RES) / (8 * ROWS_PER_WARP);   // 32768
    fused_kernel<<<M_BLOCKS + z_blocks, 256>>>(
        m, ln_m_w, ln_m_b, z, x, ln_z_w, ln_z_b, lin_w, lin_b, out_m, out_z);
}